// round 1
// baseline (speedup 1.0000x reference)
#include <cuda_runtime.h>
#include <cuda_bf16.h>
#include <math.h>

// Problem constants
#define BATCH 8
#define CIN   256
#define COUT  256
#define H     64
#define W     64
#define H2    128
#define W2    128
#define KTAP  9
#define Y_ELEMS (BATCH*COUT*H*W)          // 8388608

// Scratch (device globals — no cudaMalloc allowed)
__device__ float g_offmask[BATCH * 27 * H * W];       // 3.5 MB
__device__ float g_wt[CIN * KTAP * COUT];             // w_dcn transposed to [c][k][o], 2.4 MB

// ---------------------------------------------------------------------------
// Kernel 0: transpose w_dcn [O][C][K] -> g_wt [C][K][O]
// ---------------------------------------------------------------------------
__global__ void k_transpose_w(const float* __restrict__ w) {
    int i = blockIdx.x * 256 + threadIdx.x;
    if (i < COUT * CIN * KTAP) {
        int o = i / (CIN * KTAP);
        int r = i - o * (CIN * KTAP);
        int c = r / KTAP;
        int k = r - c * KTAP;
        g_wt[(c * KTAP + k) * COUT + o] = w[i];
    }
}

// ---------------------------------------------------------------------------
// Kernel 1: 3x3 conv x[8,256,64,64] * w_off[27,256,3,3] + b_off -> g_offmask
// Block: (b, 4-row tile). 256 threads, 1 pixel each, 27(->28) accumulators.
// ---------------------------------------------------------------------------
__global__ void __launch_bounds__(256) k_off(const float* __restrict__ x,
                                             const float* __restrict__ w_off,
                                             const float* __restrict__ b_off) {
    __shared__ float xs[6][66];
    __shared__ float ws[9 * 28];   // [kk][co], padded 27->28 for float4

    int tid = threadIdx.x;
    int bidx = blockIdx.x;                 // 128 blocks
    int b = bidx >> 4;
    int h0 = (bidx & 15) * 4;
    int r = tid >> 6;
    int wc = tid & 63;

    float acc[28];
#pragma unroll
    for (int i = 0; i < 28; i++) acc[i] = (i < 27) ? b_off[i] : 0.f;

    for (int c = 0; c < CIN; c++) {
        __syncthreads();
        if (tid < 243) {
            int co = tid / 9, kk = tid - co * 9;
            ws[kk * 28 + co] = w_off[co * (CIN * 9) + c * 9 + kk];
        }
        const float* xp = x + ((b * CIN + c) << 12);
        for (int i = tid; i < 396; i += 256) {
            int rr = i / 66, col = i - rr * 66;
            int hh = h0 - 1 + rr, ww = col - 1;
            float v = 0.f;
            if (hh >= 0 && hh < H && ww >= 0 && ww < W) v = xp[(hh << 6) + ww];
            xs[rr][col] = v;
        }
        __syncthreads();
#pragma unroll
        for (int kh = 0; kh < 3; kh++)
#pragma unroll
            for (int kw = 0; kw < 3; kw++) {
                float xv = xs[r + kh][wc + kw];
                const float4* w4 = (const float4*)&ws[(kh * 3 + kw) * 28];
#pragma unroll
                for (int q = 0; q < 7; q++) {
                    float4 wv = w4[q];
                    acc[q * 4 + 0] += xv * wv.x;
                    acc[q * 4 + 1] += xv * wv.y;
                    acc[q * 4 + 2] += xv * wv.z;
                    acc[q * 4 + 3] += xv * wv.w;
                }
            }
    }
    int h = h0 + r;
#pragma unroll
    for (int co = 0; co < 27; co++)
        g_offmask[((b * 27 + co) << 12) + (h << 6) + wc] = acc[co];
}

// ---------------------------------------------------------------------------
// Kernel 2: modulated deformable conv + BN1 + ReLU -> yout (d_out region 0)
// Block: 32 consecutive pixels (same b,h) x all 256 output channels.
// Phase A: per-tap clamped corner indices + mask-folded bilinear weights.
// Phase B: per input channel: gather 288 vals -> smem, GEMM vs g_wt[c].
// Thread: 8 outputs x 4 pixels.
// ---------------------------------------------------------------------------
__global__ void __launch_bounds__(256) k_deform(const float* __restrict__ x,
                                                const float* __restrict__ g1,
                                                const float* __restrict__ be1,
                                                const float* __restrict__ m1,
                                                const float* __restrict__ v1,
                                                float* __restrict__ yout) {
    __shared__ int4   s_idx[288];
    __shared__ float4 s_wgt[288];
    __shared__ float4 s_val4[72];      // 288 floats, [k*32 + j]
    __shared__ float4 s_w4[576];       // 2304 floats, [k*256 + o]

    int tid = threadIdx.x;
    int pix0 = blockIdx.x << 5;        // 1024 blocks
    int b = pix0 >> 12;
    int h = (pix0 >> 6) & 63;
    int w0 = pix0 & 63;                // 0 or 32

    // ---- Phase A: tap table ----
    for (int e = tid; e < 288; e += 256) {
        int k = e >> 5, j = e & 31;
        int wq = w0 + j;
        const float* om = g_offmask + (b * 27) * 4096 + (h << 6) + wq;
        float dy = om[k * 4096];
        float dx = om[(9 + k) * 4096];
        float ms = om[(18 + k) * 4096];
        float m = 1.f / (1.f + expf(-ms));
        float py = dy + (float)(k / 3 - 1 + h);
        float px = dx + (float)(k % 3 - 1 + wq);
        float fy = floorf(py), fx = floorf(px);
        float wy = py - fy, wx = px - fx;
        int y0 = (int)fy, x0 = (int)fx;
        int y1 = y0 + 1, x1 = x0 + 1;
        float vy0 = (y0 >= 0 && y0 < H) ? 1.f : 0.f;
        float vy1 = (y1 >= 0 && y1 < H) ? 1.f : 0.f;
        float vx0 = (x0 >= 0 && x0 < W) ? 1.f : 0.f;
        float vx1 = (x1 >= 0 && x1 < W) ? 1.f : 0.f;
        int cy0 = min(max(y0, 0), H - 1), cy1 = min(max(y1, 0), H - 1);
        int cx0 = min(max(x0, 0), W - 1), cx1 = min(max(x1, 0), W - 1);
        int4 id;
        id.x = (cy0 << 6) + cx0;
        id.y = (cy0 << 6) + cx1;
        id.z = (cy1 << 6) + cx0;
        id.w = (cy1 << 6) + cx1;
        s_idx[e] = id;
        float4 wv;
        wv.x = (1.f - wy) * (1.f - wx) * m * vy0 * vx0;
        wv.y = (1.f - wy) * wx * m * vy0 * vx1;
        wv.z = wy * (1.f - wx) * m * vy1 * vx0;
        wv.w = wy * wx * m * vy1 * vx1;
        s_wgt[e] = wv;
    }

    float acc[8][4];
#pragma unroll
    for (int i = 0; i < 8; i++)
#pragma unroll
        for (int j = 0; j < 4; j++) acc[i][j] = 0.f;

    int og = tid >> 3;     // 32 groups of 8 outputs
    int pg = tid & 7;      // 8 groups of 4 pixels
    const float* xb = x + (b << 20);
    float* s_val = (float*)s_val4;
    const float* s_w = (const float*)s_w4;

    for (int c = 0; c < CIN; c++) {
        __syncthreads();
        const float4* wg = (const float4*)(g_wt + c * (KTAP * COUT));
        for (int i = tid; i < 576; i += 256) s_w4[i] = wg[i];
        const float* xp = xb + (c << 12);
        for (int e = tid; e < 288; e += 256) {
            int4 id = s_idx[e];
            float4 wv = s_wgt[e];
            s_val[e] = wv.x * xp[id.x] + wv.y * xp[id.y] +
                       wv.z * xp[id.z] + wv.w * xp[id.w];
        }
        __syncthreads();
#pragma unroll
        for (int k = 0; k < 9; k++) {
            float4 v = s_val4[(k << 3) + pg];
#pragma unroll
            for (int q = 0; q < 2; q++) {
                float4 wv = ((const float4*)s_w)[(k << 6) + og * 2 + q];
                acc[q * 4 + 0][0] += wv.x * v.x; acc[q * 4 + 0][1] += wv.x * v.y;
                acc[q * 4 + 0][2] += wv.x * v.z; acc[q * 4 + 0][3] += wv.x * v.w;
                acc[q * 4 + 1][0] += wv.y * v.x; acc[q * 4 + 1][1] += wv.y * v.y;
                acc[q * 4 + 1][2] += wv.y * v.z; acc[q * 4 + 1][3] += wv.y * v.w;
                acc[q * 4 + 2][0] += wv.z * v.x; acc[q * 4 + 2][1] += wv.z * v.y;
                acc[q * 4 + 2][2] += wv.z * v.z; acc[q * 4 + 2][3] += wv.z * v.w;
                acc[q * 4 + 3][0] += wv.w * v.x; acc[q * 4 + 3][1] += wv.w * v.y;
                acc[q * 4 + 3][2] += wv.w * v.z; acc[q * 4 + 3][3] += wv.w * v.w;
            }
        }
    }

    // ---- epilogue: BN1 + ReLU, float4 stores ----
#pragma unroll
    for (int q = 0; q < 2; q++)
#pragma unroll
        for (int oi = 0; oi < 4; oi++) {
            int o = (og << 3) + (q << 2) + oi;
            float sc = g1[o] * rsqrtf(v1[o] + 1e-5f);
            float mu = m1[o], bt = be1[o];
            float4 r;
            r.x = fmaxf((acc[q * 4 + oi][0] - mu) * sc + bt, 0.f);
            r.y = fmaxf((acc[q * 4 + oi][1] - mu) * sc + bt, 0.f);
            r.z = fmaxf((acc[q * 4 + oi][2] - mu) * sc + bt, 0.f);
            r.w = fmaxf((acc[q * 4 + oi][3] - mu) * sc + bt, 0.f);
            *((float4*)(yout + (((b << 8) + o) << 12) + (h << 6) + w0 + (pg << 2))) = r;
        }
}

// ---------------------------------------------------------------------------
// Kernel 3: transposed conv (4x4, stride2, pad2) + BN2 + ReLU
// Decomposed into 4 parity classes (a = p%2, qb = q%2); each is a 2x2 conv.
// Block: one class, one batch, one class-row pp; 64 pixels x 256 outputs.
// Thread: 8 outputs x 8 pixels.
// up[b,o,p,q] = sum_c sum_{s,t} y[b,c,pp+s+a-1, qq+qb+t-1] * w_up[c,o,3-(a+2s),3-(qb+2t)]
// ---------------------------------------------------------------------------
__global__ void __launch_bounds__(256) k_deconv(const float* __restrict__ y,
                                                const float* __restrict__ w_up,
                                                const float* __restrict__ g2,
                                                const float* __restrict__ be2,
                                                const float* __restrict__ m2,
                                                const float* __restrict__ v2,
                                                float* __restrict__ up) {
    __shared__ float s_y[2][66];
    __shared__ float4 s_w[256];    // per o: (s0t0, s0t1, s1t0, s1t1)

    int tid = threadIdx.x;
    int bidx = blockIdx.x;          // 2048 blocks
    int pp = bidx & 63;
    int b  = (bidx >> 6) & 7;
    int qb = (bidx >> 9) & 1;
    int a  = (bidx >> 10) & 1;
    int p = 2 * pp + a;
    int iy0 = pp + a - 1;           // rows iy0 (s=0), iy0+1 (s=1)

    int og = tid >> 3;
    int pg = tid & 7;
    int qq0 = pg << 3;

    float acc[8][8];
#pragma unroll
    for (int i = 0; i < 8; i++)
#pragma unroll
        for (int j = 0; j < 8; j++) acc[i][j] = 0.f;

    int wr0 = (3 - a) * 4;   // row offset in w for s=0
    int wr1 = (1 - a) * 4;   // row offset for s=1
    int wc0 = 3 - qb;        // col for t=0
    int wc1 = 1 - qb;        // col for t=1

    for (int c = 0; c < CIN; c++) {
        __syncthreads();
        for (int i = tid; i < 132; i += 256) {
            int rr = i / 66, col = i - rr * 66;
            int iy = iy0 + rr, ix = col - 1;
            float vv = 0.f;
            if (iy >= 0 && iy < H && ix >= 0 && ix < W)
                vv = y[(((b << 8) + c) << 12) + (iy << 6) + ix];
            s_y[rr][col] = vv;
        }
        {
            int o = tid;
            const float* wb = w_up + ((c << 8) + o) * 16;
            float4 wv;
            wv.x = wb[wr0 + wc0];
            wv.y = wb[wr0 + wc1];
            wv.z = wb[wr1 + wc0];
            wv.w = wb[wr1 + wc1];
            s_w[o] = wv;
        }
        __syncthreads();

        float r0[9], r1[9];
#pragma unroll
        for (int t = 0; t < 9; t++) {
            r0[t] = s_y[0][qq0 + qb + t];
            r1[t] = s_y[1][qq0 + qb + t];
        }
#pragma unroll
        for (int oo = 0; oo < 8; oo++) {
            float4 wv = s_w[(og << 3) + oo];
#pragma unroll
            for (int j = 0; j < 8; j++)
                acc[oo][j] += wv.x * r0[j] + wv.y * r0[j + 1] +
                              wv.z * r1[j] + wv.w * r1[j + 1];
        }
    }

    // ---- epilogue: BN2 + ReLU ----
#pragma unroll
    for (int oo = 0; oo < 8; oo++) {
        int o = (og << 3) + oo;
        float sc = g2[o] * rsqrtf(v2[o] + 1e-5f);
        float mu = m2[o], bt = be2[o];
        float* ob = up + (((b << 8) + o) << 14) + (p << 7) + qb;
#pragma unroll
        for (int j = 0; j < 8; j++) {
            int qq = qq0 + j;
            ob[qq << 1] = fmaxf((acc[oo][j] - mu) * sc + bt, 0.f);
        }
    }
}

// ---------------------------------------------------------------------------
extern "C" void kernel_launch(void* const* d_in, const int* in_sizes, int n_in,
                              void* d_out, int out_size) {
    const float* x      = (const float*)d_in[0];
    const float* w_off  = (const float*)d_in[1];
    const float* b_off  = (const float*)d_in[2];
    const float* w_dcn  = (const float*)d_in[3];
    const float* gamma1 = (const float*)d_in[4];
    const float* beta1  = (const float*)d_in[5];
    const float* mean1  = (const float*)d_in[6];
    const float* var1   = (const float*)d_in[7];
    const float* w_up   = (const float*)d_in[8];
    const float* gamma2 = (const float*)d_in[9];
    const float* beta2  = (const float*)d_in[10];
    const float* mean2  = (const float*)d_in[11];
    const float* var2   = (const float*)d_in[12];

    float* yout  = (float*)d_out;
    float* upout = yout + Y_ELEMS;

    k_transpose_w<<<(COUT * CIN * KTAP + 255) / 256, 256>>>(w_dcn);
    k_off<<<BATCH * 16, 256>>>(x, w_off, b_off);
    k_deform<<<(BATCH * H * W) / 32, 256>>>(x, gamma1, beta1, mean1, var1, yout);
    k_deconv<<<4 * BATCH * 64, 256>>>(yout, w_up, gamma2, beta2, mean2, var2, upout);
}

// round 3
// speedup vs baseline: 1.9744x; 1.9744x over previous
#include <cuda_runtime.h>
#include <cuda_bf16.h>
#include <math.h>
#include <stdint.h>

// Problem constants
#define BATCH 8
#define CIN   256
#define COUT  256
#define H     64
#define W     64
#define H2    128
#define W2    128
#define KTAP  9
#define Y_ELEMS (BATCH*COUT*H*W)          // 8388608

// Scratch (device globals — no cudaMalloc allowed)
__device__ float g_offmask[BATCH * 27 * H * W];       // 3.5 MB
__device__ float g_wt[CIN * KTAP * COUT];             // w_dcn transposed to [c][k][o], 2.4 MB
// Deconv A in per-thread MMA fragment order (tf32 bits):
// [cls(4)][mt(2)][ks(128)][m16t(8)][lane(32)][frag(4)]  = 4 MB
__device__ uint32_t g_wA[4 * 2 * 128 * 8 * 32 * 4];

// ---------------------------------------------------------------------------
// MMA helpers (sm_80 baseline PTX — legal on plain sm_103 target)
// ---------------------------------------------------------------------------
__device__ __forceinline__ uint32_t f2tf32(float v) {
    uint32_t u;
    asm("cvt.rna.tf32.f32 %0, %1;" : "=r"(u) : "f"(v));
    return u;
}
__device__ __forceinline__ void mma_tf32(float& d0, float& d1, float& d2, float& d3,
                                         uint32_t a0, uint32_t a1, uint32_t a2, uint32_t a3,
                                         uint32_t b0, uint32_t b1) {
    asm volatile("mma.sync.aligned.m16n8k8.row.col.f32.tf32.tf32.f32 "
                 "{%0,%1,%2,%3}, {%4,%5,%6,%7}, {%8,%9}, {%0,%1,%2,%3};"
                 : "+f"(d0), "+f"(d1), "+f"(d2), "+f"(d3)
                 : "r"(a0), "r"(a1), "r"(a2), "r"(a3), "r"(b0), "r"(b1));
}

// ---------------------------------------------------------------------------
// Kernel 0a: transpose w_dcn [O][C][K] -> g_wt [C][K][O]
// ---------------------------------------------------------------------------
__global__ void k_transpose_w(const float* __restrict__ w) {
    int i = blockIdx.x * 256 + threadIdx.x;
    if (i < COUT * CIN * KTAP) {
        int o = i / (CIN * KTAP);
        int r = i - o * (CIN * KTAP);
        int c = r / KTAP;
        int k = r - c * KTAP;
        g_wt[(c * KTAP + k) * COUT + o] = w[i];
    }
}

// ---------------------------------------------------------------------------
// Kernel 0b: bake deconv A into per-thread tf32 fragment order.
// kk = c*4 + s*2 + t;  A[o][kk] = w_up[c][o][3-(a+2s)][3-(qb+2t)]
// Fragment (m16n8k8 tf32, row-major A): a0=(g,tg) a1=(g+8,tg) a2=(g,tg+4) a3=(g+8,tg+4)
// ---------------------------------------------------------------------------
__global__ void k_prep_wA(const float* __restrict__ w_up) {
    int e = blockIdx.x * 256 + threadIdx.x;   // 1,048,576 total
    int frag = e & 3;
    int lane = (e >> 2) & 31;
    int m16t = (e >> 7) & 7;
    int ks   = (e >> 10) & 127;
    int mt   = (e >> 17) & 1;
    int cls  = e >> 18;
    int a = cls >> 1, qb = cls & 1;
    int g = lane >> 2, tg = lane & 3;
    int row = m16t * 16 + g + 8 * (frag & 1);
    int kcol = tg + 4 * (frag >> 1);
    int kk = ks * 8 + kcol;
    int c = kk >> 2, s = (kk >> 1) & 1, t = kk & 1;
    int o = mt * 128 + row;
    float val = w_up[((c << 8) + o) * 16 + (3 - (a + 2 * s)) * 4 + (3 - (qb + 2 * t))];
    g_wA[e] = f2tf32(val);
}

// ---------------------------------------------------------------------------
// Kernel 1: 3x3 conv x * w_off + b_off -> g_offmask   (unchanged from R0)
// ---------------------------------------------------------------------------
__global__ void __launch_bounds__(256) k_off(const float* __restrict__ x,
                                             const float* __restrict__ w_off,
                                             const float* __restrict__ b_off) {
    __shared__ float xs[6][66];
    __shared__ float ws[9 * 28];

    int tid = threadIdx.x;
    int bidx = blockIdx.x;
    int b = bidx >> 4;
    int h0 = (bidx & 15) * 4;
    int r = tid >> 6;
    int wc = tid & 63;

    float acc[28];
#pragma unroll
    for (int i = 0; i < 28; i++) acc[i] = (i < 27) ? b_off[i] : 0.f;

    for (int c = 0; c < CIN; c++) {
        __syncthreads();
        if (tid < 243) {
            int co = tid / 9, kk = tid - co * 9;
            ws[kk * 28 + co] = w_off[co * (CIN * 9) + c * 9 + kk];
        }
        const float* xp = x + ((b * CIN + c) << 12);
        for (int i = tid; i < 396; i += 256) {
            int rr = i / 66, col = i - rr * 66;
            int hh = h0 - 1 + rr, ww = col - 1;
            float v = 0.f;
            if (hh >= 0 && hh < H && ww >= 0 && ww < W) v = xp[(hh << 6) + ww];
            xs[rr][col] = v;
        }
        __syncthreads();
#pragma unroll
        for (int kh = 0; kh < 3; kh++)
#pragma unroll
            for (int kw = 0; kw < 3; kw++) {
                float xv = xs[r + kh][wc + kw];
                const float4* w4 = (const float4*)&ws[(kh * 3 + kw) * 28];
#pragma unroll
                for (int q = 0; q < 7; q++) {
                    float4 wv = w4[q];
                    acc[q * 4 + 0] += xv * wv.x;
                    acc[q * 4 + 1] += xv * wv.y;
                    acc[q * 4 + 2] += xv * wv.z;
                    acc[q * 4 + 3] += xv * wv.w;
                }
            }
    }
    int h = h0 + r;
#pragma unroll
    for (int co = 0; co < 27; co++)
        g_offmask[((b * 27 + co) << 12) + (h << 6) + wc] = acc[co];
}

// ---------------------------------------------------------------------------
// Kernel 2: modulated deformable conv + BN1 + ReLU -> yout   (unchanged R0)
// ---------------------------------------------------------------------------
__global__ void __launch_bounds__(256) k_deform(const float* __restrict__ x,
                                                const float* __restrict__ g1,
                                                const float* __restrict__ be1,
                                                const float* __restrict__ m1,
                                                const float* __restrict__ v1,
                                                float* __restrict__ yout) {
    __shared__ int4   s_idx[288];
    __shared__ float4 s_wgt[288];
    __shared__ float4 s_val4[72];
    __shared__ float4 s_w4[576];

    int tid = threadIdx.x;
    int pix0 = blockIdx.x << 5;
    int b = pix0 >> 12;
    int h = (pix0 >> 6) & 63;
    int w0 = pix0 & 63;

    for (int e = tid; e < 288; e += 256) {
        int k = e >> 5, j = e & 31;
        int wq = w0 + j;
        const float* om = g_offmask + (b * 27) * 4096 + (h << 6) + wq;
        float dy = om[k * 4096];
        float dx = om[(9 + k) * 4096];
        float ms = om[(18 + k) * 4096];
        float m = 1.f / (1.f + expf(-ms));
        float py = dy + (float)(k / 3 - 1 + h);
        float px = dx + (float)(k % 3 - 1 + wq);
        float fy = floorf(py), fx = floorf(px);
        float wy = py - fy, wx = px - fx;
        int y0 = (int)fy, x0 = (int)fx;
        int y1 = y0 + 1, x1 = x0 + 1;
        float vy0 = (y0 >= 0 && y0 < H) ? 1.f : 0.f;
        float vy1 = (y1 >= 0 && y1 < H) ? 1.f : 0.f;
        float vx0 = (x0 >= 0 && x0 < W) ? 1.f : 0.f;
        float vx1 = (x1 >= 0 && x1 < W) ? 1.f : 0.f;
        int cy0 = min(max(y0, 0), H - 1), cy1 = min(max(y1, 0), H - 1);
        int cx0 = min(max(x0, 0), W - 1), cx1 = min(max(x1, 0), W - 1);
        int4 id;
        id.x = (cy0 << 6) + cx0;
        id.y = (cy0 << 6) + cx1;
        id.z = (cy1 << 6) + cx0;
        id.w = (cy1 << 6) + cx1;
        s_idx[e] = id;
        float4 wv;
        wv.x = (1.f - wy) * (1.f - wx) * m * vy0 * vx0;
        wv.y = (1.f - wy) * wx * m * vy0 * vx1;
        wv.z = wy * (1.f - wx) * m * vy1 * vx0;
        wv.w = wy * wx * m * vy1 * vx1;
        s_wgt[e] = wv;
    }

    float acc[8][4];
#pragma unroll
    for (int i = 0; i < 8; i++)
#pragma unroll
        for (int j = 0; j < 4; j++) acc[i][j] = 0.f;

    int og = tid >> 3;
    int pg = tid & 7;
    const float* xb = x + (b << 20);
    float* s_val = (float*)s_val4;
    const float* s_w = (const float*)s_w4;

    for (int c = 0; c < CIN; c++) {
        __syncthreads();
        const float4* wg = (const float4*)(g_wt + c * (KTAP * COUT));
        for (int i = tid; i < 576; i += 256) s_w4[i] = wg[i];
        const float* xp = xb + (c << 12);
        for (int e = tid; e < 288; e += 256) {
            int4 id = s_idx[e];
            float4 wv = s_wgt[e];
            s_val[e] = wv.x * xp[id.x] + wv.y * xp[id.y] +
                       wv.z * xp[id.z] + wv.w * xp[id.w];
        }
        __syncthreads();
#pragma unroll
        for (int k = 0; k < 9; k++) {
            float4 v = s_val4[(k << 3) + pg];
#pragma unroll
            for (int q = 0; q < 2; q++) {
                float4 wv = ((const float4*)s_w)[(k << 6) + og * 2 + q];
                acc[q * 4 + 0][0] += wv.x * v.x; acc[q * 4 + 0][1] += wv.x * v.y;
                acc[q * 4 + 0][2] += wv.x * v.z; acc[q * 4 + 0][3] += wv.x * v.w;
                acc[q * 4 + 1][0] += wv.y * v.x; acc[q * 4 + 1][1] += wv.y * v.y;
                acc[q * 4 + 1][2] += wv.y * v.z; acc[q * 4 + 1][3] += wv.y * v.w;
                acc[q * 4 + 2][0] += wv.z * v.x; acc[q * 4 + 2][1] += wv.z * v.y;
                acc[q * 4 + 2][2] += wv.z * v.z; acc[q * 4 + 2][3] += wv.z * v.w;
                acc[q * 4 + 3][0] += wv.w * v.x; acc[q * 4 + 3][1] += wv.w * v.y;
                acc[q * 4 + 3][2] += wv.w * v.z; acc[q * 4 + 3][3] += wv.w * v.w;
            }
        }
    }

#pragma unroll
    for (int q = 0; q < 2; q++)
#pragma unroll
        for (int oi = 0; oi < 4; oi++) {
            int o = (og << 3) + (q << 2) + oi;
            float sc = g1[o] * rsqrtf(v1[o] + 1e-5f);
            float mu = m1[o], bt = be1[o];
            float4 r;
            r.x = fmaxf((acc[q * 4 + oi][0] - mu) * sc + bt, 0.f);
            r.y = fmaxf((acc[q * 4 + oi][1] - mu) * sc + bt, 0.f);
            r.z = fmaxf((acc[q * 4 + oi][2] - mu) * sc + bt, 0.f);
            r.w = fmaxf((acc[q * 4 + oi][3] - mu) * sc + bt, 0.f);
            *((float4*)(yout + (((b << 8) + o) << 12) + (h << 6) + w0 + (pg << 2))) = r;
        }
}

// ---------------------------------------------------------------------------
// Kernel 3: transposed conv via mma.sync tf32 GEMM + BN2 + ReLU.
// Grid 2048: [cls(4)][b(8)][mt(2)][pt(32)].
// CTA: M=128 (o-half), N=128 (2 pp-rows x 64 qq), K=1024, chunk=16.
// 8 warps = 2(M) x 4(N); warp tile 64x32; acc 4x4 frags of m16n8.
// B smem [n(128)][k(16 pad 20)], double buffered, tf32 bits.
// ---------------------------------------------------------------------------
__global__ void __launch_bounds__(256) k_deconv_mma(const float* __restrict__ y,
                                                    const float* __restrict__ g2,
                                                    const float* __restrict__ be2,
                                                    const float* __restrict__ m2,
                                                    const float* __restrict__ v2,
                                                    float* __restrict__ up) {
    __shared__ uint32_t Bs[2][128 * 20];

    int tid = threadIdx.x;
    int wid = tid >> 5, lane = tid & 31;
    int g = lane >> 2, tg = lane & 3;
    int warpM = wid >> 2, warpN = wid & 3;

    int bidx = blockIdx.x;
    int pt  = bidx & 31;
    int mt  = (bidx >> 5) & 1;
    int b   = (bidx >> 6) & 7;
    int cls = bidx >> 9;
    int a = cls >> 1, qb = cls & 1;
    int pp0 = pt << 1;

    // --- B fill mapping: thread = (nb 0..15) x (kl 0..15); 8 n each ---
    int kl = tid & 15;
    int nb = tid >> 4;
    int c_l = kl >> 2, s = (kl >> 1) & 1, t = kl & 1;
    int pr = nb >> 3;
    int qq0 = (nb & 7) << 3;
    int n0 = nb << 3;
    int iy = pp0 + pr + s + a - 1;
    bool rowok = (iy >= 0 && iy < H);
    const float* ybase = y + ((b << 8) << 12) + (iy << 6);
    int ix0 = qq0 + qb - 1 + t;

    float acc[4][4][4];
#pragma unroll
    for (int i = 0; i < 4; i++)
#pragma unroll
        for (int j = 0; j < 4; j++)
#pragma unroll
            for (int f = 0; f < 4; f++) acc[i][j][f] = 0.f;

    // fill chunk 0
    {
        const float* yr = ybase + (c_l << 12);
#pragma unroll
        for (int j = 0; j < 8; j++) {
            int ix = ix0 + j;
            float v = (rowok && ix >= 0 && ix < W) ? __ldg(yr + ix) : 0.f;
            Bs[0][(n0 + j) * 20 + kl] = f2tf32(v);
        }
    }
    __syncthreads();

    const uint32_t* Afrag = g_wA + (cls * 2 + mt) * (128 * 8 * 32 * 4);

    for (int chunk = 0; chunk < 64; chunk++) {
        int cur = chunk & 1;
        // prefetch next chunk's y values
        float pv[8];
        if (chunk < 63) {
            const float* yr = ybase + (((chunk + 1) * 4 + c_l) << 12);
#pragma unroll
            for (int j = 0; j < 8; j++) {
                int ix = ix0 + j;
                pv[j] = (rowok && ix >= 0 && ix < W) ? __ldg(yr + ix) : 0.f;
            }
        }
        // A fragments for both ksteps (uint4 per mtile, fragment-ordered gmem)
        uint32_t af[2][4][4];
#pragma unroll
        for (int ksv = 0; ksv < 2; ksv++)
#pragma unroll
            for (int mtl = 0; mtl < 4; mtl++) {
                uint4 q = *(const uint4*)(Afrag +
                    ((((chunk * 2 + ksv) * 8) + warpM * 4 + mtl) * 32 + lane) * 4);
                af[ksv][mtl][0] = q.x; af[ksv][mtl][1] = q.y;
                af[ksv][mtl][2] = q.z; af[ksv][mtl][3] = q.w;
            }
        // MMA
#pragma unroll
        for (int ksv = 0; ksv < 2; ksv++) {
            uint32_t bf[4][2];
#pragma unroll
            for (int nt = 0; nt < 4; nt++) {
                int nrow = warpN * 32 + nt * 8 + g;
                bf[nt][0] = Bs[cur][nrow * 20 + ksv * 8 + tg];
                bf[nt][1] = Bs[cur][nrow * 20 + ksv * 8 + tg + 4];
            }
#pragma unroll
            for (int mtl = 0; mtl < 4; mtl++)
#pragma unroll
                for (int nt = 0; nt < 4; nt++)
                    mma_tf32(acc[mtl][nt][0], acc[mtl][nt][1], acc[mtl][nt][2], acc[mtl][nt][3],
                             af[ksv][mtl][0], af[ksv][mtl][1], af[ksv][mtl][2], af[ksv][mtl][3],
                             bf[nt][0], bf[nt][1]);
        }
        // store prefetched B into other buffer
        if (chunk < 63) {
            int nxt = cur ^ 1;
#pragma unroll
            for (int j = 0; j < 8; j++)
                Bs[nxt][(n0 + j) * 20 + kl] = f2tf32(pv[j]);
        }
        __syncthreads();
    }

    // --- epilogue: BN2 + ReLU ---
    float sc[4][2], sh[4][2];
#pragma unroll
    for (int mtl = 0; mtl < 4; mtl++)
#pragma unroll
        for (int hh = 0; hh < 2; hh++) {
            int o = mt * 128 + warpM * 64 + mtl * 16 + g + hh * 8;
            float s_ = __ldg(g2 + o) * rsqrtf(__ldg(v2 + o) + 1e-5f);
            sc[mtl][hh] = s_;
            sh[mtl][hh] = __ldg(be2 + o) - __ldg(m2 + o) * s_;
        }
#pragma unroll
    for (int mtl = 0; mtl < 4; mtl++)
#pragma unroll
        for (int hh = 0; hh < 2; hh++) {
            int o = mt * 128 + warpM * 64 + mtl * 16 + g + hh * 8;
            float* ob = up + (((b << 8) + o) << 14);
#pragma unroll
            for (int nt = 0; nt < 4; nt++)
#pragma unroll
                for (int cc = 0; cc < 2; cc++) {
                    int n = warpN * 32 + nt * 8 + 2 * tg + cc;
                    int prr = n >> 6, qqv = n & 63;
                    int p = ((pp0 + prr) << 1) + a;
                    int qv = (qqv << 1) + qb;
                    float v = acc[mtl][nt][hh * 2 + cc];
                    ob[(p << 7) + qv] = fmaxf(fmaf(v, sc[mtl][hh], sh[mtl][hh]), 0.f);
                }
        }
}

// ---------------------------------------------------------------------------
extern "C" void kernel_launch(void* const* d_in, const int* in_sizes, int n_in,
                              void* d_out, int out_size) {
    const float* x      = (const float*)d_in[0];
    const float* w_off  = (const float*)d_in[1];
    const float* b_off  = (const float*)d_in[2];
    const float* w_dcn  = (const float*)d_in[3];
    const float* gamma1 = (const float*)d_in[4];
    const float* beta1  = (const float*)d_in[5];
    const float* mean1  = (const float*)d_in[6];
    const float* var1   = (const float*)d_in[7];
    const float* w_up   = (const float*)d_in[8];
    const float* gamma2 = (const float*)d_in[9];
    const float* beta2  = (const float*)d_in[10];
    const float* mean2  = (const float*)d_in[11];
    const float* var2   = (const float*)d_in[12];

    float* yout  = (float*)d_out;
    float* upout = yout + Y_ELEMS;

    k_transpose_w<<<(COUT * CIN * KTAP + 255) / 256, 256>>>(w_dcn);
    k_prep_wA<<<4096, 256>>>(w_up);
    k_off<<<BATCH * 16, 256>>>(x, w_off, b_off);
    k_deform<<<(BATCH * H * W) / 32, 256>>>(x, gamma1, beta1, mean1, var1, yout);
    k_deconv_mma<<<2048, 256>>>(yout, gamma2, beta2, mean2, var2, upout);
}

// round 4
// speedup vs baseline: 2.2737x; 1.1516x over previous
#include <cuda_runtime.h>
#include <cuda_bf16.h>
#include <math.h>
#include <stdint.h>

// Problem constants
#define BATCH 8
#define CIN   256
#define COUT  256
#define H     64
#define W     64
#define H2    128
#define W2    128
#define KTAP  9
#define Y_ELEMS (BATCH*COUT*H*W)          // 8388608

// Scratch (device globals — no cudaMalloc allowed)
__device__ float g_offmask[BATCH * 27 * H * W];       // 3.5 MB
// Deconv A in per-thread MMA fragment order (tf32 bits):
// [cls(4)][mt(2)][ks(128)][m16t(8)][lane(32)][frag(4)]  = 4 MB
__device__ uint32_t g_wA[4 * 2 * 128 * 8 * 32 * 4];
// Deform A in per-thread MMA fragment order (tf32 bits):
// [mt(2)][ks(288)][m16t(8)][lane(32)][frag(4)]  = 2.36 MB
__device__ uint32_t g_wD[2 * 288 * 8 * 32 * 4];

// ---------------------------------------------------------------------------
// MMA helpers (sm_80 baseline PTX — legal on plain sm_103 target)
// ---------------------------------------------------------------------------
__device__ __forceinline__ uint32_t f2tf32(float v) {
    uint32_t u;
    asm("cvt.rna.tf32.f32 %0, %1;" : "=r"(u) : "f"(v));
    return u;
}
__device__ __forceinline__ void mma_tf32(float& d0, float& d1, float& d2, float& d3,
                                         uint32_t a0, uint32_t a1, uint32_t a2, uint32_t a3,
                                         uint32_t b0, uint32_t b1) {
    asm volatile("mma.sync.aligned.m16n8k8.row.col.f32.tf32.tf32.f32 "
                 "{%0,%1,%2,%3}, {%4,%5,%6,%7}, {%8,%9}, {%0,%1,%2,%3};"
                 : "+f"(d0), "+f"(d1), "+f"(d2), "+f"(d3)
                 : "r"(a0), "r"(a1), "r"(a2), "r"(a3), "r"(b0), "r"(b1));
}

// ---------------------------------------------------------------------------
// Kernel 0b: bake deconv A into per-thread tf32 fragment order.
// kk = c*4 + s*2 + t;  A[o][kk] = w_up[c][o][3-(a+2s)][3-(qb+2t)]
// ---------------------------------------------------------------------------
__global__ void k_prep_wA(const float* __restrict__ w_up) {
    int e = blockIdx.x * 256 + threadIdx.x;   // 1,048,576 total
    int frag = e & 3;
    int lane = (e >> 2) & 31;
    int m16t = (e >> 7) & 7;
    int ks   = (e >> 10) & 127;
    int mt   = (e >> 17) & 1;
    int cls  = e >> 18;
    int a = cls >> 1, qb = cls & 1;
    int g = lane >> 2, tg = lane & 3;
    int row = m16t * 16 + g + 8 * (frag & 1);
    int kcol = tg + 4 * (frag >> 1);
    int kk = ks * 8 + kcol;
    int c = kk >> 2, s = (kk >> 1) & 1, t = kk & 1;
    int o = mt * 128 + row;
    float val = w_up[((c << 8) + o) * 16 + (3 - (a + 2 * s)) * 4 + (3 - (qb + 2 * t))];
    g_wA[e] = f2tf32(val);
}

// ---------------------------------------------------------------------------
// Kernel 0c: bake deform A (w_dcn) into per-thread tf32 fragment order.
// kk = c*9 + k  (K = 2304 = 288 ksteps of 8)
// ---------------------------------------------------------------------------
__global__ void k_prep_wD(const float* __restrict__ w_dcn) {
    int e = blockIdx.x * 256 + threadIdx.x;   // 589,824 total
    if (e >= 2 * 288 * 8 * 32 * 4) return;
    int frag = e & 3;
    int lane = (e >> 2) & 31;
    int m16t = (e >> 7) & 7;
    int rest = e >> 10;                 // 0..575
    int ks = rest % 288;
    int mt = rest / 288;
    int g = lane >> 2, tg = lane & 3;
    int row = m16t * 16 + g + 8 * (frag & 1);
    int kcol = tg + 4 * (frag >> 1);
    int kk = ks * 8 + kcol;             // 0..2303
    int c = kk / 9;
    int k = kk - c * 9;
    int o = mt * 128 + row;
    g_wD[e] = f2tf32(w_dcn[(o * 256 + c) * 9 + k]);
}

// ---------------------------------------------------------------------------
// Kernel 1: 3x3 conv x * w_off + b_off -> g_offmask
// ---------------------------------------------------------------------------
__global__ void __launch_bounds__(256) k_off(const float* __restrict__ x,
                                             const float* __restrict__ w_off,
                                             const float* __restrict__ b_off) {
    __shared__ float xs[6][66];
    __shared__ float ws[9 * 28];

    int tid = threadIdx.x;
    int bidx = blockIdx.x;
    int b = bidx >> 4;
    int h0 = (bidx & 15) * 4;
    int r = tid >> 6;
    int wc = tid & 63;

    float acc[28];
#pragma unroll
    for (int i = 0; i < 28; i++) acc[i] = (i < 27) ? b_off[i] : 0.f;

    for (int c = 0; c < CIN; c++) {
        __syncthreads();
        if (tid < 243) {
            int co = tid / 9, kk = tid - co * 9;
            ws[kk * 28 + co] = w_off[co * (CIN * 9) + c * 9 + kk];
        }
        const float* xp = x + ((b * CIN + c) << 12);
        for (int i = tid; i < 396; i += 256) {
            int rr = i / 66, col = i - rr * 66;
            int hh = h0 - 1 + rr, ww = col - 1;
            float v = 0.f;
            if (hh >= 0 && hh < H && ww >= 0 && ww < W) v = xp[(hh << 6) + ww];
            xs[rr][col] = v;
        }
        __syncthreads();
#pragma unroll
        for (int kh = 0; kh < 3; kh++)
#pragma unroll
            for (int kw = 0; kw < 3; kw++) {
                float xv = xs[r + kh][wc + kw];
                const float4* w4 = (const float4*)&ws[(kh * 3 + kw) * 28];
#pragma unroll
                for (int q = 0; q < 7; q++) {
                    float4 wv = w4[q];
                    acc[q * 4 + 0] += xv * wv.x;
                    acc[q * 4 + 1] += xv * wv.y;
                    acc[q * 4 + 2] += xv * wv.z;
                    acc[q * 4 + 3] += xv * wv.w;
                }
            }
    }
    int h = h0 + r;
#pragma unroll
    for (int co = 0; co < 27; co++)
        g_offmask[((b * 27 + co) << 12) + (h << 6) + wc] = acc[co];
}

// ---------------------------------------------------------------------------
// Kernel 2 (NEW): deformable conv via mma.sync tf32 GEMM + BN1 + ReLU.
// Grid 512: [b(8)][mt(2)][pt(32)].  CTA: M=128 (o-half), N=128 pixels
// (2 rows), K=2304 (c*9+tap), chunk=16 (2 ksteps).
// Phase A: tap table (idx ushort4 + weight float4) per (pixel, tap).
// B fill: 4 gathers from x (L2) per value, double buffered.
// ---------------------------------------------------------------------------
__global__ void __launch_bounds__(256) k_deform_mma(const float* __restrict__ x,
                                                    const float* __restrict__ g1,
                                                    const float* __restrict__ be1,
                                                    const float* __restrict__ m1,
                                                    const float* __restrict__ v1,
                                                    float* __restrict__ yout) {
    __shared__ ushort4 s_idx[1152];     // [pix(128)][tap(9)]
    __shared__ float4  s_wgt[1152];
    __shared__ uint32_t Bs[2][128 * 20];

    int tid = threadIdx.x;
    int wid = tid >> 5, lane = tid & 31;
    int g = lane >> 2, tg = lane & 3;
    int warpM = wid >> 2, warpN = wid & 3;

    int bidx = blockIdx.x;
    int pt = bidx & 31;
    int mt = (bidx >> 5) & 1;
    int b  = bidx >> 6;
    int pix0 = pt << 7;
    int h0 = pix0 >> 6;                 // two rows: h0, h0+1

    // ---- Phase A: tap table ----
    for (int e = tid; e < 1152; e += 256) {
        int pix = e / 9, tap = e - pix * 9;
        int h = h0 + (pix >> 6), w = pix & 63;
        const float* om = g_offmask + (b * 27) * 4096 + (h << 6) + w;
        float dy = om[tap * 4096];
        float dx = om[(9 + tap) * 4096];
        float ms = om[(18 + tap) * 4096];
        float m = 1.f / (1.f + expf(-ms));
        float py = dy + (float)(tap / 3 - 1 + h);
        float px = dx + (float)(tap % 3 - 1 + w);
        float fy = floorf(py), fx = floorf(px);
        float wy = py - fy, wx = px - fx;
        int y0 = (int)fy, x0 = (int)fx;
        int y1 = y0 + 1, x1 = x0 + 1;
        float vy0 = (y0 >= 0 && y0 < H) ? 1.f : 0.f;
        float vy1 = (y1 >= 0 && y1 < H) ? 1.f : 0.f;
        float vx0 = (x0 >= 0 && x0 < W) ? 1.f : 0.f;
        float vx1 = (x1 >= 0 && x1 < W) ? 1.f : 0.f;
        int cy0 = min(max(y0, 0), H - 1), cy1 = min(max(y1, 0), H - 1);
        int cx0 = min(max(x0, 0), W - 1), cx1 = min(max(x1, 0), W - 1);
        ushort4 id;
        id.x = (unsigned short)((cy0 << 6) + cx0);
        id.y = (unsigned short)((cy0 << 6) + cx1);
        id.z = (unsigned short)((cy1 << 6) + cx0);
        id.w = (unsigned short)((cy1 << 6) + cx1);
        s_idx[e] = id;
        float4 wv;
        wv.x = (1.f - wy) * (1.f - wx) * m * vy0 * vx0;
        wv.y = (1.f - wy) * wx * m * vy0 * vx1;
        wv.z = wy * (1.f - wx) * m * vy1 * vx0;
        wv.w = wy * wx * m * vy1 * vx1;
        s_wgt[e] = wv;
    }
    __syncthreads();

    // ---- B fill mapping: 16 kl x 16 nb, 8 pixels each ----
    int kl = tid & 15;
    int nb = tid >> 4;
    int n0 = nb << 3;
    const float* xb = x + (b << 20);

    float acc[4][4][4];
#pragma unroll
    for (int i = 0; i < 4; i++)
#pragma unroll
        for (int j = 0; j < 4; j++)
#pragma unroll
            for (int f = 0; f < 4; f++) acc[i][j][f] = 0.f;

    // fill chunk 0
    {
        int kk = kl;
        int c = kk / 9, tap = kk - c * 9;
        const float* xp = xb + (c << 12);
#pragma unroll
        for (int j = 0; j < 8; j++) {
            int e = (n0 + j) * 9 + tap;
            ushort4 id = s_idx[e];
            float4 wv = s_wgt[e];
            float v = wv.x * __ldg(xp + id.x) + wv.y * __ldg(xp + id.y) +
                      wv.z * __ldg(xp + id.z) + wv.w * __ldg(xp + id.w);
            Bs[0][(n0 + j) * 20 + kl] = f2tf32(v);
        }
    }
    __syncthreads();

    const uint32_t* Afrag = g_wD + mt * (288 * 8 * 32 * 4);

    for (int chunk = 0; chunk < 144; chunk++) {
        int cur = chunk & 1;
        // prefetch next chunk's gathered values
        float pv[8];
        if (chunk < 143) {
            int kk = (chunk + 1) * 16 + kl;
            int c = kk / 9, tap = kk - c * 9;
            const float* xp = xb + (c << 12);
#pragma unroll
            for (int j = 0; j < 8; j++) {
                int e = (n0 + j) * 9 + tap;
                ushort4 id = s_idx[e];
                float4 wv = s_wgt[e];
                pv[j] = wv.x * __ldg(xp + id.x) + wv.y * __ldg(xp + id.y) +
                        wv.z * __ldg(xp + id.z) + wv.w * __ldg(xp + id.w);
            }
        }
        // MMA over 2 ksteps
#pragma unroll
        for (int ksv = 0; ksv < 2; ksv++) {
            uint32_t af[4][4];
#pragma unroll
            for (int mtl = 0; mtl < 4; mtl++) {
                uint4 q = *(const uint4*)(Afrag +
                    ((((chunk * 2 + ksv) * 8) + warpM * 4 + mtl) * 32 + lane) * 4);
                af[mtl][0] = q.x; af[mtl][1] = q.y; af[mtl][2] = q.z; af[mtl][3] = q.w;
            }
            uint32_t bf[4][2];
#pragma unroll
            for (int nt = 0; nt < 4; nt++) {
                int nrow = warpN * 32 + nt * 8 + g;
                bf[nt][0] = Bs[cur][nrow * 20 + ksv * 8 + tg];
                bf[nt][1] = Bs[cur][nrow * 20 + ksv * 8 + tg + 4];
            }
#pragma unroll
            for (int mtl = 0; mtl < 4; mtl++)
#pragma unroll
                for (int nt = 0; nt < 4; nt++)
                    mma_tf32(acc[mtl][nt][0], acc[mtl][nt][1], acc[mtl][nt][2], acc[mtl][nt][3],
                             af[mtl][0], af[mtl][1], af[mtl][2], af[mtl][3],
                             bf[nt][0], bf[nt][1]);
        }
        if (chunk < 143) {
            int nxt = cur ^ 1;
#pragma unroll
            for (int j = 0; j < 8; j++)
                Bs[nxt][(n0 + j) * 20 + kl] = f2tf32(pv[j]);
        }
        __syncthreads();
    }

    // ---- epilogue: BN1 + ReLU ----
#pragma unroll
    for (int mtl = 0; mtl < 4; mtl++)
#pragma unroll
        for (int hh = 0; hh < 2; hh++) {
            int o = mt * 128 + warpM * 64 + mtl * 16 + g + hh * 8;
            float s_ = __ldg(g1 + o) * rsqrtf(__ldg(v1 + o) + 1e-5f);
            float sh = __ldg(be1 + o) - __ldg(m1 + o) * s_;
            float* ob = yout + (((b << 8) + o) << 12) + pix0;
#pragma unroll
            for (int nt = 0; nt < 4; nt++)
#pragma unroll
                for (int cc = 0; cc < 2; cc++) {
                    int n = warpN * 32 + nt * 8 + 2 * tg + cc;
                    float v = acc[mtl][nt][hh * 2 + cc];
                    ob[n] = fmaxf(fmaf(v, s_, sh), 0.f);
                }
        }
}

// ---------------------------------------------------------------------------
// Kernel 3: transposed conv via mma.sync tf32 GEMM + BN2 + ReLU  (R3, passing)
// ---------------------------------------------------------------------------
__global__ void __launch_bounds__(256) k_deconv_mma(const float* __restrict__ y,
                                                    const float* __restrict__ g2,
                                                    const float* __restrict__ be2,
                                                    const float* __restrict__ m2,
                                                    const float* __restrict__ v2,
                                                    float* __restrict__ up) {
    __shared__ uint32_t Bs[2][128 * 20];

    int tid = threadIdx.x;
    int wid = tid >> 5, lane = tid & 31;
    int g = lane >> 2, tg = lane & 3;
    int warpM = wid >> 2, warpN = wid & 3;

    int bidx = blockIdx.x;
    int pt  = bidx & 31;
    int mt  = (bidx >> 5) & 1;
    int b   = (bidx >> 6) & 7;
    int cls = bidx >> 9;
    int a = cls >> 1, qb = cls & 1;
    int pp0 = pt << 1;

    int kl = tid & 15;
    int nb = tid >> 4;
    int c_l = kl >> 2, s = (kl >> 1) & 1, t = kl & 1;
    int pr = nb >> 3;
    int qq0 = (nb & 7) << 3;
    int n0 = nb << 3;
    int iy = pp0 + pr + s + a - 1;
    bool rowok = (iy >= 0 && iy < H);
    const float* ybase = y + ((b << 8) << 12) + (iy << 6);
    int ix0 = qq0 + qb - 1 + t;

    float acc[4][4][4];
#pragma unroll
    for (int i = 0; i < 4; i++)
#pragma unroll
        for (int j = 0; j < 4; j++)
#pragma unroll
            for (int f = 0; f < 4; f++) acc[i][j][f] = 0.f;

    {
        const float* yr = ybase + (c_l << 12);
#pragma unroll
        for (int j = 0; j < 8; j++) {
            int ix = ix0 + j;
            float v = (rowok && ix >= 0 && ix < W) ? __ldg(yr + ix) : 0.f;
            Bs[0][(n0 + j) * 20 + kl] = f2tf32(v);
        }
    }
    __syncthreads();

    const uint32_t* Afrag = g_wA + (cls * 2 + mt) * (128 * 8 * 32 * 4);

    for (int chunk = 0; chunk < 64; chunk++) {
        int cur = chunk & 1;
        float pv[8];
        if (chunk < 63) {
            const float* yr = ybase + (((chunk + 1) * 4 + c_l) << 12);
#pragma unroll
            for (int j = 0; j < 8; j++) {
                int ix = ix0 + j;
                pv[j] = (rowok && ix >= 0 && ix < W) ? __ldg(yr + ix) : 0.f;
            }
        }
        uint32_t af[2][4][4];
#pragma unroll
        for (int ksv = 0; ksv < 2; ksv++)
#pragma unroll
            for (int mtl = 0; mtl < 4; mtl++) {
                uint4 q = *(const uint4*)(Afrag +
                    ((((chunk * 2 + ksv) * 8) + warpM * 4 + mtl) * 32 + lane) * 4);
                af[ksv][mtl][0] = q.x; af[ksv][mtl][1] = q.y;
                af[ksv][mtl][2] = q.z; af[ksv][mtl][3] = q.w;
            }
#pragma unroll
        for (int ksv = 0; ksv < 2; ksv++) {
            uint32_t bf[4][2];
#pragma unroll
            for (int nt = 0; nt < 4; nt++) {
                int nrow = warpN * 32 + nt * 8 + g;
                bf[nt][0] = Bs[cur][nrow * 20 + ksv * 8 + tg];
                bf[nt][1] = Bs[cur][nrow * 20 + ksv * 8 + tg + 4];
            }
#pragma unroll
            for (int mtl = 0; mtl < 4; mtl++)
#pragma unroll
                for (int nt = 0; nt < 4; nt++)
                    mma_tf32(acc[mtl][nt][0], acc[mtl][nt][1], acc[mtl][nt][2], acc[mtl][nt][3],
                             af[ksv][mtl][0], af[ksv][mtl][1], af[ksv][mtl][2], af[ksv][mtl][3],
                             bf[nt][0], bf[nt][1]);
        }
        if (chunk < 63) {
            int nxt = cur ^ 1;
#pragma unroll
            for (int j = 0; j < 8; j++)
                Bs[nxt][(n0 + j) * 20 + kl] = f2tf32(pv[j]);
        }
        __syncthreads();
    }

    float sc[4][2], sh[4][2];
#pragma unroll
    for (int mtl = 0; mtl < 4; mtl++)
#pragma unroll
        for (int hh = 0; hh < 2; hh++) {
            int o = mt * 128 + warpM * 64 + mtl * 16 + g + hh * 8;
            float s_ = __ldg(g2 + o) * rsqrtf(__ldg(v2 + o) + 1e-5f);
            sc[mtl][hh] = s_;
            sh[mtl][hh] = __ldg(be2 + o) - __ldg(m2 + o) * s_;
        }
#pragma unroll
    for (int mtl = 0; mtl < 4; mtl++)
#pragma unroll
        for (int hh = 0; hh < 2; hh++) {
            int o = mt * 128 + warpM * 64 + mtl * 16 + g + hh * 8;
            float* ob = up + (((b << 8) + o) << 14);
#pragma unroll
            for (int nt = 0; nt < 4; nt++)
#pragma unroll
                for (int cc = 0; cc < 2; cc++) {
                    int n = warpN * 32 + nt * 8 + 2 * tg + cc;
                    int prr = n >> 6, qqv = n & 63;
                    int p = ((pp0 + prr) << 1) + a;
                    int qv = (qqv << 1) + qb;
                    float v = acc[mtl][nt][hh * 2 + cc];
                    ob[(p << 7) + qv] = fmaxf(fmaf(v, sc[mtl][hh], sh[mtl][hh]), 0.f);
                }
        }
}

// ---------------------------------------------------------------------------
extern "C" void kernel_launch(void* const* d_in, const int* in_sizes, int n_in,
                              void* d_out, int out_size) {
    const float* x      = (const float*)d_in[0];
    const float* w_off  = (const float*)d_in[1];
    const float* b_off  = (const float*)d_in[2];
    const float* w_dcn  = (const float*)d_in[3];
    const float* gamma1 = (const float*)d_in[4];
    const float* beta1  = (const float*)d_in[5];
    const float* mean1  = (const float*)d_in[6];
    const float* var1   = (const float*)d_in[7];
    const float* w_up   = (const float*)d_in[8];
    const float* gamma2 = (const float*)d_in[9];
    const float* beta2  = (const float*)d_in[10];
    const float* mean2  = (const float*)d_in[11];
    const float* var2   = (const float*)d_in[12];

    float* yout  = (float*)d_out;
    float* upout = yout + Y_ELEMS;

    k_prep_wA<<<4096, 256>>>(w_up);
    k_prep_wD<<<2304, 256>>>(w_dcn);
    k_off<<<BATCH * 16, 256>>>(x, w_off, b_off);
    k_deform_mma<<<512, 256>>>(x, gamma1, beta1, mean1, var1, yout);
    k_deconv_mma<<<2048, 256>>>(yout, gamma2, beta2, mean2, var2, upout);
}